// round 4
// baseline (speedup 1.0000x reference)
#include <cuda_runtime.h>

// ---------------------------------------------------------------------------
// WindowGrapherPyg fused kernel, R3: 512 threads/CTA + conflict-free Gram.
// One CTA per 8x8 window; xw/Q/K/V resident in smem; f32x2 packed GEMMs.
// ---------------------------------------------------------------------------

typedef unsigned long long u64;

namespace {
constexpr int Bc = 2, Cc = 192, Hc = 192, Wc = 192;
constexpr int WS = 8, NN = 64, KK = 9, HEADS = 8, DH = 24;
constexpr int NWH = Hc / WS, NWW = Wc / WS;         // 24 x 24
constexpr int WB = Bc * NWH * NWW;                  // 1152 windows
constexpr int STR = 196;                            // padded row stride
constexpr int NT = 512;
constexpr int XW_FLOATS = NN * STR;                 // 12544
constexpr int WT_FLOATS = 32 * Cc;                  // 6144 (aliases Gram 64*64)
constexpr size_t SMEM_BYTES =
    (size_t)(4 * XW_FLOATS + WT_FLOATS + NN) * sizeof(float) +
    (size_t)(NN * KK) * sizeof(int);                // 227,840 B
constexpr float INV_SQRT_DH = 0.20412414523193154f;
}

__device__ __forceinline__ u64 dup2f(float a) {
  u64 r; asm("mov.b64 %0, {%1, %1};" : "=l"(r) : "f"(a)); return r;
}
__device__ __forceinline__ u64 pack2f(float x, float y) {
  u64 r; asm("mov.b64 %0, {%1, %2};" : "=l"(r) : "f"(x), "f"(y)); return r;
}
__device__ __forceinline__ void fma2(u64& d, u64 a, u64 b) {
  asm("fma.rn.f32x2 %0, %1, %2, %0;" : "+l"(d) : "l"(a), "l"(b));
}
__device__ __forceinline__ float2 unpack2(u64 v) {
  float2 o; asm("mov.b64 {%0, %1}, %2;" : "=f"(o.x), "=f"(o.y) : "l"(v));
  return o;
}

// acc[4][3]: rows ty*4+r, col pairs (2tx+64j, 2tx+64j+1).
__device__ __forceinline__ void gemm_core(const float* __restrict__ sXW,
                                          const float* __restrict__ Wg,
                                          const float* __restrict__ bias,
                                          float* __restrict__ sWT,
                                          u64 acc[4][3], int tid) {
  const int ty = tid >> 5, tx = tid & 31;
#pragma unroll
  for (int j = 0; j < 3; j++) {
    float2 b = *(const float2*)(bias + 2 * tx + 64 * j);
    u64 bp = pack2f(b.x, b.y);
#pragma unroll
    for (int r = 0; r < 4; r++) acc[r][j] = bp;
  }
  float4 pf[3];
#pragma unroll
  for (int i = 0; i < 3; i++) {
    int t = tid + NT * i, kr = t / 48, cq = t - kr * 48;
    pf[i] = *(const float4*)(Wg + kr * Cc + cq * 4);
  }
  const float* arow = sXW + ty * 4 * STR;
  for (int ko = 0; ko < Cc; ko += 32) {
    __syncthreads();  // prior consumers of sWT done
#pragma unroll
    for (int i = 0; i < 3; i++) {
      int t = tid + NT * i, kr = t / 48, cq = t - kr * 48;
      *(float4*)(sWT + kr * Cc + cq * 4) = pf[i];
    }
    __syncthreads();
    if (ko + 32 < Cc) {  // prefetch next W tile under the compute below
#pragma unroll
      for (int i = 0; i < 3; i++) {
        int t = tid + NT * i, kr = t / 48, cq = t - kr * 48;
        pf[i] = *(const float4*)(Wg + (ko + 32 + kr) * Cc + cq * 4);
      }
    }
#pragma unroll
    for (int kq = 0; kq < 8; kq++) {
      float4 a4[4];
#pragma unroll
      for (int r = 0; r < 4; r++)
        a4[r] = *(const float4*)(arow + r * STR + ko + kq * 4);
#pragma unroll
      for (int kk = 0; kk < 4; kk++) {
        u64 b2[3];
#pragma unroll
        for (int j = 0; j < 3; j++)
          b2[j] = *(const u64*)(sWT + (kq * 4 + kk) * Cc + 2 * tx + 64 * j);
#pragma unroll
        for (int r = 0; r < 4; r++) {
          float av = (kk == 0) ? a4[r].x : (kk == 1) ? a4[r].y
                    : (kk == 2) ? a4[r].z : a4[r].w;
          u64 a2 = dup2f(av);
#pragma unroll
          for (int j = 0; j < 3; j++) fma2(acc[r][j], a2, b2[j]);
        }
      }
    }
  }
}

__device__ __forceinline__ void gemm_to_smem(const float* __restrict__ sXW,
                                             const float* __restrict__ Wg,
                                             const float* __restrict__ bias,
                                             float* __restrict__ sWT,
                                             float* __restrict__ dst, int tid) {
  u64 acc[4][3];
  gemm_core(sXW, Wg, bias, sWT, acc, tid);
  const int ty = tid >> 5, tx = tid & 31;
#pragma unroll
  for (int r = 0; r < 4; r++)
#pragma unroll
    for (int j = 0; j < 3; j++)
      *(float2*)(dst + (ty * 4 + r) * STR + 2 * tx + 64 * j) =
          unpack2(acc[r][j]);
  __syncthreads();
}

__device__ __forceinline__ void gemm_skip_out(const float* __restrict__ sXW,
                                              const float* __restrict__ Wg,
                                              const float* __restrict__ bias,
                                              float* __restrict__ sWT,
                                              const float* __restrict__ sAttn,
                                              float* __restrict__ out,
                                              int b, int h0, int w0, int tid) {
  u64 acc[4][3];
  gemm_core(sXW, Wg, bias, sWT, acc, tid);
  const int ty = tid >> 5, tx = tid & 31;
  const int nh = ty >> 1, nwb = (ty & 1) * 4;
#pragma unroll
  for (int j = 0; j < 3; j++) {
    const int c = 2 * tx + 64 * j;
    float lo[4], hi[4];
#pragma unroll
    for (int r = 0; r < 4; r++) {
      int g = ty * 4 + r;
      float2 v = unpack2(acc[r][j]);
      lo[r] = v.x + sAttn[g * STR + c];
      hi[r] = v.y + sAttn[g * STR + c + 1];
    }
    float* d0 = out + ((b * Cc + c) * Hc + h0 + nh) * Wc + w0 + nwb;
    *(float4*)d0 = make_float4(lo[0], lo[1], lo[2], lo[3]);
    float* d1 = out + ((b * Cc + c + 1) * Hc + h0 + nh) * Wc + w0 + nwb;
    *(float4*)d1 = make_float4(hi[0], hi[1], hi[2], hi[3]);
  }
}

__global__ void __launch_bounds__(NT, 1)
wg_kernel(const float* __restrict__ x,
          const float* __restrict__ Wq, const float* __restrict__ bq,
          const float* __restrict__ Wk, const float* __restrict__ bk,
          const float* __restrict__ Wvw, const float* __restrict__ bv,
          const float* __restrict__ Wsk, const float* __restrict__ bsk,
          float* __restrict__ out) {
  extern __shared__ float sm[];
  float* sXW = sm;
  float* sQ = sXW + XW_FLOATS;
  float* sK = sQ + XW_FLOATS;
  float* sV = sK + XW_FLOATS;
  float* sWT = sV + XW_FLOATS;   // 6144 floats; first 4096 alias Gram
  float* sG = sWT;
  float* sSq = sWT + WT_FLOATS;  // 64 floats
  int* sIdx = (int*)(sSq + NN);  // 64*9 ints

  const int tid = threadIdx.x;
  const int w = blockIdx.x;
  const int b = w / (NWH * NWW);
  const int rem = w - b * (NWH * NWW);
  const int wh = rem / NWW, ww = rem - wh * NWW;
  const int h0 = wh * WS, w0 = ww * WS;

  // ---- Phase A: gather window nodes ----
#pragma unroll
  for (int i = 0; i < 3; i++) {
    int t = tid + NT * i;          // 0..1535 : (c, nh)
    int c = t >> 3, nh = t & 7;
    const float* src = x + ((b * Cc + c) * Hc + h0 + nh) * Wc + w0;
    float4 v0 = *(const float4*)src;
    float4 v1 = *(const float4*)(src + 4);
    float* d = sXW + (nh * 8) * STR + c;
    d[0 * STR] = v0.x; d[1 * STR] = v0.y; d[2 * STR] = v0.z; d[3 * STR] = v0.w;
    d[4 * STR] = v1.x; d[5 * STR] = v1.y; d[6 * STR] = v1.z; d[7 * STR] = v1.w;
  }
  __syncthreads();

  // ---- Phase B1: Gram matrix, 256 threads, 4x4 spread tiles, k-pair fma2.
  // rows {tn+16i}, cols {tm+16j}: conflict-free LDS.128 (lane stride 784B).
  if (tid < 256) {
    const int tn = tid >> 4, tm = tid & 15;
    u64 acc2[4][4] = {};
#pragma unroll 2
    for (int k = 0; k < Cc; k += 4) {
      ulonglong2 a[4], bb[4];
#pragma unroll
      for (int i = 0; i < 4; i++)
        a[i] = *(const ulonglong2*)(sXW + (tn + 16 * i) * STR + k);
#pragma unroll
      for (int j = 0; j < 4; j++)
        bb[j] = *(const ulonglong2*)(sXW + (tm + 16 * j) * STR + k);
#pragma unroll
      for (int i = 0; i < 4; i++)
#pragma unroll
        for (int j = 0; j < 4; j++) {
          fma2(acc2[i][j], a[i].x, bb[j].x);
          fma2(acc2[i][j], a[i].y, bb[j].y);
        }
    }
#pragma unroll
    for (int i = 0; i < 4; i++)
#pragma unroll
      for (int j = 0; j < 4; j++) {
        float2 v = unpack2(acc2[i][j]);
        sG[(tn + 16 * i) * NN + tm + 16 * j] = v.x + v.y;
      }
  }
  __syncthreads();
  if (tid < NN) sSq[tid] = sG[tid * (NN + 1)];
  __syncthreads();

  // ---- Phase B2: top-9 nearest neighbors (stable, exact fp32) ----
  if (tid < NN) {
    const int n = tid;
    unsigned long long mask = 1ull << n;  // exclude self
    const float sqn = sSq[n];
    const float* grow = sG + n * NN;
#pragma unroll 1
    for (int kk = 0; kk < KK; kk++) {
      float best = 3.0e38f;
      int bi = 0;
#pragma unroll 4
      for (int m = 0; m < NN; m++) {
        float d = sqn + sSq[m] - 2.0f * grow[m];
        if ((mask >> m) & 1ull) d = 3.9e38f;
        if (d < best) { best = d; bi = m; }  // '<' = lowest index wins ties
      }
      mask |= 1ull << bi;
      sIdx[n * KK + kk] = bi;
    }
  }
  __syncthreads();

  // ---- Phase C: Q, K, V projections (f32x2) ----
  gemm_to_smem(sXW, Wq, bq, sWT, sQ, tid);
  gemm_to_smem(sXW, Wk, bk, sWT, sK, tid);
  gemm_to_smem(sXW, Wvw, bv, sWT, sV, tid);

  // ---- Phase D: 9-neighbor softmax attention; 512 thr = one (n,h) each ----
  {
    const int n = tid & (NN - 1);
    const int h = tid >> 6;
    const float* qp = sQ + n * STR + h * DH;
    float q[DH];
#pragma unroll
    for (int d4 = 0; d4 < DH / 4; d4++) {
      float4 v = *(const float4*)(qp + d4 * 4);
      q[d4 * 4 + 0] = v.x; q[d4 * 4 + 1] = v.y;
      q[d4 * 4 + 2] = v.z; q[d4 * 4 + 3] = v.w;
    }
    float sc[KK];
    int nb[KK];
#pragma unroll
    for (int kk = 0; kk < KK; kk++) {
      int m = sIdx[n * KK + kk];
      nb[kk] = m;
      const float* kp = sK + m * STR + h * DH;
      float s = 0.0f;
#pragma unroll
      for (int d4 = 0; d4 < DH / 4; d4++) {
        float4 v = *(const float4*)(kp + d4 * 4);
        s = fmaf(q[d4 * 4 + 0], v.x, s);
        s = fmaf(q[d4 * 4 + 1], v.y, s);
        s = fmaf(q[d4 * 4 + 2], v.z, s);
        s = fmaf(q[d4 * 4 + 3], v.w, s);
      }
      sc[kk] = s * INV_SQRT_DH;
    }
    float mx = sc[0];
#pragma unroll
    for (int kk = 1; kk < KK; kk++) mx = fmaxf(mx, sc[kk]);
    float ssum = 0.0f;
#pragma unroll
    for (int kk = 0; kk < KK; kk++) { sc[kk] = __expf(sc[kk] - mx); ssum += sc[kk]; }
    const float inv = 1.0f / ssum;
    float o[DH] = {};
#pragma unroll
    for (int kk = 0; kk < KK; kk++) {
      float a = sc[kk] * inv;
      const float* vp = sV + nb[kk] * STR + h * DH;
#pragma unroll
      for (int d4 = 0; d4 < DH / 4; d4++) {
        float4 v = *(const float4*)(vp + d4 * 4);
        o[d4 * 4 + 0] = fmaf(a, v.x, o[d4 * 4 + 0]);
        o[d4 * 4 + 1] = fmaf(a, v.y, o[d4 * 4 + 1]);
        o[d4 * 4 + 2] = fmaf(a, v.z, o[d4 * 4 + 2]);
        o[d4 * 4 + 3] = fmaf(a, v.w, o[d4 * 4 + 3]);
      }
    }
    float* op = sQ + n * STR + h * DH;  // attn out overwrites own q segment
#pragma unroll
    for (int d4 = 0; d4 < DH / 4; d4++)
      *(float4*)(op + d4 * 4) =
          make_float4(o[d4 * 4 + 0], o[d4 * 4 + 1], o[d4 * 4 + 2], o[d4 * 4 + 3]);
  }
  // first __syncthreads inside gemm_skip_out guards sQ reads

  // ---- Phase E: skip GEMM + attn add + scatter to [B,C,H,W] ----
  gemm_skip_out(sXW, Wsk, bsk, sWT, sQ, out, b, h0, w0, tid);
}

extern "C" void kernel_launch(void* const* d_in, const int* in_sizes, int n_in,
                              void* d_out, int out_size) {
  const float* x   = (const float*)d_in[0];
  const float* Wq  = (const float*)d_in[1];
  const float* bq  = (const float*)d_in[2];
  const float* Wk  = (const float*)d_in[3];
  const float* bk  = (const float*)d_in[4];
  const float* Wv  = (const float*)d_in[5];
  const float* bv  = (const float*)d_in[6];
  const float* Wsk = (const float*)d_in[7];
  const float* bsk = (const float*)d_in[8];
  float* out = (float*)d_out;

  cudaFuncSetAttribute(wg_kernel, cudaFuncAttributeMaxDynamicSharedMemorySize,
                       (int)SMEM_BYTES);
  wg_kernel<<<WB, NT, SMEM_BYTES>>>(x, Wq, bq, Wk, bk, Wv, bv, Wsk, bsk, out);
}